// round 3
// baseline (speedup 1.0000x reference)
#include <cuda_runtime.h>
#include <math.h>

// Problem constants
#define IN_DIM 512
#define HID    128
#define OUT_D  64
#define MAXN   50176
#define MAXE   800000

// Scratch as __device__ globals, referenced DIRECTLY inside kernels.
__device__ float g_h[(size_t)MAXN * 128];   // GEMM output buffer
__device__ float g_x[(size_t)MAXN * 128];   // aggregated activation buffer
__device__ float g_dis[MAXN];               // 1/sqrt(deg)
__device__ int   g_deg[MAXN];
__device__ int   g_off[MAXN + 1];           // CSR row offsets (by dst)
__device__ int   g_cur[MAXN];               // fill cursors
__device__ int   g_csr[MAXE];               // src index per (dst-sorted) edge

// ---------------------------------------------------------------------------
// Graph preprocessing (adj is INT32: jax x64 is disabled by default, so the
// reference's "int64" arrays are actually materialized as int32)
// ---------------------------------------------------------------------------
__global__ void init_deg(int n) {
    int i = blockIdx.x * blockDim.x + threadIdx.x;
    if (i < n) g_deg[i] = 1;  // self loop
}

__global__ void count_deg(const int* __restrict__ dst, int e, int n) {
    int i = blockIdx.x * blockDim.x + threadIdx.x;
    if (i < e) {
        int d = dst[i];
        if ((unsigned)d < (unsigned)n) atomicAdd(&g_deg[d], 1);
    }
}

// Exclusive scan of in-degree (deg-1) into g_off; single block, chunked.
__global__ void scan_off(int n) {
    __shared__ int sdata[1024];
    __shared__ int carry_s;
    int tid = threadIdx.x;
    if (tid == 0) carry_s = 0;
    __syncthreads();
    for (int base = 0; base < n; base += 1024) {
        int i = base + tid;
        int v = (i < n) ? (g_deg[i] - 1) : 0;
        sdata[tid] = v;
        __syncthreads();
        #pragma unroll
        for (int off = 1; off < 1024; off <<= 1) {
            int t = (tid >= off) ? sdata[tid - off] : 0;
            __syncthreads();
            sdata[tid] += t;
            __syncthreads();
        }
        int incl = sdata[tid];
        int carry = carry_s;
        if (i < n) g_off[i] = carry + incl - v;  // exclusive
        __syncthreads();
        if (tid == 1023) carry_s = carry + sdata[1023];
        __syncthreads();
    }
    if (threadIdx.x == 0) g_off[n] = carry_s;
}

__global__ void dis_cur(int n) {
    int i = blockIdx.x * blockDim.x + threadIdx.x;
    if (i < n) {
        g_dis[i] = rsqrtf((float)g_deg[i]);
        g_cur[i] = g_off[i];
    }
}

__global__ void fill_csr(const int* __restrict__ src,
                         const int* __restrict__ dst, int e, int n) {
    int i = blockIdx.x * blockDim.x + threadIdx.x;
    if (i < e) {
        int d = dst[i];
        int s = src[i];
        if ((unsigned)d < (unsigned)n && (unsigned)s < (unsigned)n) {
            int pos = atomicAdd(&g_cur[d], 1);
            if (pos < MAXE) g_csr[pos] = s;
        }
    }
}

// ---------------------------------------------------------------------------
// GEMM: g_h[n,F] = X[n,K] @ W[K,F].  BM=128, BK=32, 256 threads, TM=8, TN=F/16.
// ---------------------------------------------------------------------------
template <int F>
__global__ void gemm_kernel(const float* __restrict__ Xext, int use_gx,
                            const float* __restrict__ W, int n, int K) {
    const float* __restrict__ X = use_gx ? (const float*)g_x : Xext;

    constexpr int BM = 128, BK = 32;
    constexpr int TN = F / 16, TM = 8;
    __shared__ float As[BK][BM + 1];  // transposed, padded
    __shared__ float Bs[BK][F];

    const int tid = threadIdx.x;
    const int tx = tid & 15;
    const int ty = tid >> 4;
    const int row0 = blockIdx.x * BM;

    float acc[TM][TN] = {};

    for (int k0 = 0; k0 < K; k0 += BK) {
        for (int i = tid; i < BM * BK; i += 256) {
            int m = i / BK, kk = i % BK;
            int r = row0 + m;
            As[kk][m] = (r < n) ? X[(size_t)r * K + k0 + kk] : 0.f;
        }
        for (int i = tid; i < BK * F; i += 256) {
            int kk = i / F, c = i % F;
            Bs[kk][c] = W[(size_t)(k0 + kk) * F + c];
        }
        __syncthreads();

        #pragma unroll
        for (int kk = 0; kk < BK; kk++) {
            float a[TM], b[TN];
            #pragma unroll
            for (int r = 0; r < TM; r++) a[r] = As[kk][ty * TM + r];
            #pragma unroll
            for (int c = 0; c < TN; c++) b[c] = Bs[kk][tx * TN + c];
            #pragma unroll
            for (int r = 0; r < TM; r++)
                #pragma unroll
                for (int c = 0; c < TN; c++)
                    acc[r][c] = fmaf(a[r], b[c], acc[r][c]);
        }
        __syncthreads();
    }

    #pragma unroll
    for (int r = 0; r < TM; r++) {
        int rr = row0 + ty * TM + r;
        if (rr < n) {
            #pragma unroll
            for (int c = 0; c < TN; c++)
                g_h[(size_t)rr * F + tx * TN + c] = acc[r][c];
        }
    }
}

// ---------------------------------------------------------------------------
// Aggregation: g_x[i] = relu?( dis[i]*(dis[i]*g_h[i] + sum_in dis[s]*g_h[s]) + b )
// One block per node, one thread per feature. g_h (25.6MB) fits L2.
// ---------------------------------------------------------------------------
template <int F, bool RELU>
__global__ void agg_kernel(const float* __restrict__ bias, int n) {
    int node = blockIdx.x;
    if (node >= n) return;
    int f = threadIdx.x;
    const float* __restrict__ h = (const float*)g_h;
    float dn = g_dis[node];
    float acc = dn * h[(size_t)node * F + f];
    int j = g_off[node], end = g_off[node + 1];
    for (; j < end; ++j) {
        int s = g_csr[j];
        acc = fmaf(g_dis[s], h[(size_t)s * F + f], acc);
    }
    float v = fmaf(dn, acc, bias[f]);
    if (RELU) v = fmaxf(v, 0.f);
    g_x[(size_t)node * F + f] = v;
}

// ---------------------------------------------------------------------------
// log_softmax over 64 cols of g_x, one warp per node (2 cols per lane)
// ---------------------------------------------------------------------------
__global__ void lsm_kernel(float* __restrict__ out, int n) {
    int node = blockIdx.x * (blockDim.x >> 5) + (threadIdx.x >> 5);
    int lane = threadIdx.x & 31;
    if (node >= n) return;
    const float* __restrict__ in = (const float*)g_x;
    float v0 = in[(size_t)node * 64 + lane];
    float v1 = in[(size_t)node * 64 + lane + 32];
    float m = fmaxf(v0, v1);
    #pragma unroll
    for (int o = 16; o; o >>= 1) m = fmaxf(m, __shfl_xor_sync(0xffffffff, m, o));
    float s = expf(v0 - m) + expf(v1 - m);
    #pragma unroll
    for (int o = 16; o; o >>= 1) s += __shfl_xor_sync(0xffffffff, s, o);
    float l = m + logf(s);
    out[(size_t)node * 64 + lane] = v0 - l;
    out[(size_t)node * 64 + lane + 32] = v1 - l;
}

// ---------------------------------------------------------------------------
extern "C" void kernel_launch(void* const* d_in, const int* in_sizes, int n_in,
                              void* d_out, int out_size) {
    const float* feats = (const float*)d_in[0];
    const int*   adj   = (const int*)d_in[1];     // int32! (jax x64 disabled)
    const float* W1    = (const float*)d_in[2];
    const float* b1    = (const float*)d_in[3];
    const float* W2    = (const float*)d_in[4];
    const float* b2    = (const float*)d_in[5];
    const float* W3    = (const float*)d_in[6];
    const float* b3    = (const float*)d_in[7];
    float*       out   = (float*)d_out;

    const int N = in_sizes[0] / IN_DIM;
    const int E = in_sizes[1] / 2;
    const int* src = adj;
    const int* dst = adj + E;

    // --- graph preprocessing (CSR by dst) ---
    init_deg<<<(N + 255) / 256, 256>>>(N);
    count_deg<<<(E + 255) / 256, 256>>>(dst, E, N);
    scan_off<<<1, 1024>>>(N);
    dis_cur<<<(N + 255) / 256, 256>>>(N);
    fill_csr<<<(E + 255) / 256, 256>>>(src, dst, E, N);

    // --- layer 1: 512 -> 128, relu ---
    gemm_kernel<128><<<(N + 127) / 128, 256>>>(feats, 0, W1, N, IN_DIM);
    agg_kernel<128, true><<<N, 128>>>(b1, N);

    // --- layer 2: 128 -> 128, relu ---
    gemm_kernel<128><<<(N + 127) / 128, 256>>>(nullptr, 1, W2, N, HID);
    agg_kernel<128, true><<<N, 128>>>(b2, N);

    // --- layer 3: 128 -> 64, log_softmax ---
    gemm_kernel<64><<<(N + 127) / 128, 256>>>(nullptr, 1, W3, N, HID);
    agg_kernel<64, false><<<N, 64>>>(b3, N);
    lsm_kernel<<<(N + 7) / 8, 256>>>(out, N);
}

// round 4
// speedup vs baseline: 1.6227x; 1.6227x over previous
#include <cuda_runtime.h>
#include <math.h>

#define IN_DIM 512
#define HID    128
#define MAXN   50176
#define MAXE   800000
#define SCAN_BLK 1024

// Device-global scratch (no allocation allowed in kernel_launch).
__device__ float g_h[(size_t)MAXN * 128];   // GEMM output
__device__ float g_x[(size_t)MAXN * 128];   // aggregated activations
__device__ float g_dis[MAXN];               // 1/sqrt(deg)
__device__ int   g_deg[MAXN];
__device__ int   g_off[MAXN + 1];           // CSR offsets (by dst)
__device__ int   g_slot[MAXE];              // per-edge slot within its dst list
__device__ int   g_csr[MAXE];               // src per (dst-grouped) edge
__device__ int   g_bsum[64];
__device__ int   g_boff[64];

// ---------------------------------------------------------------------------
// Graph preprocessing
// ---------------------------------------------------------------------------
__global__ void init_deg(int n) {
    int i = blockIdx.x * blockDim.x + threadIdx.x;
    if (i < n) g_deg[i] = 1;  // self loop
}

// count in-degree AND record each edge's slot within its destination's list
__global__ void count_deg(const int* __restrict__ dst, int e, int n) {
    int i = blockIdx.x * blockDim.x + threadIdx.x;
    if (i < e) {
        int d = dst[i];
        if ((unsigned)d < (unsigned)n) {
            int old = atomicAdd(&g_deg[d], 1);   // >=1 because of self loop
            g_slot[i] = old - 1;
        }
    }
}

// Two-level scan of (deg-1): per-block exclusive scan + block sums
__global__ void scan_partial(int n) {
    __shared__ int s[SCAN_BLK];
    int b = blockIdx.x, tid = threadIdx.x;
    int i = b * SCAN_BLK + tid;
    int v = (i < n) ? (g_deg[i] - 1) : 0;
    s[tid] = v;
    __syncthreads();
    #pragma unroll
    for (int o = 1; o < SCAN_BLK; o <<= 1) {
        int t = (tid >= o) ? s[tid - o] : 0;
        __syncthreads();
        s[tid] += t;
        __syncthreads();
    }
    if (i < n) g_off[i] = s[tid] - v;   // exclusive within block
    if (tid == SCAN_BLK - 1) g_bsum[b] = s[tid];
}

__global__ void scan_bsum(int nb, int n) {
    __shared__ int s[64];
    int tid = threadIdx.x;  // 64 threads
    int v = (tid < nb) ? g_bsum[tid] : 0;
    s[tid] = v;
    __syncthreads();
    #pragma unroll
    for (int o = 1; o < 64; o <<= 1) {
        int t = (tid >= o) ? s[tid - o] : 0;
        __syncthreads();
        s[tid] += t;
        __syncthreads();
    }
    if (tid < nb) g_boff[tid] = s[tid] - v;
    if (tid == 63) g_off[n] = s[63];
}

__global__ void add_off_dis(int n) {
    int i = blockIdx.x * blockDim.x + threadIdx.x;
    if (i < n) {
        g_off[i] += g_boff[i >> 10];
        g_dis[i] = rsqrtf((float)g_deg[i]);
    }
}

__global__ void fill_csr(const int* __restrict__ src,
                         const int* __restrict__ dst, int e, int n) {
    int i = blockIdx.x * blockDim.x + threadIdx.x;
    if (i < e) {
        int d = dst[i];
        int s = src[i];
        if ((unsigned)d < (unsigned)n && (unsigned)s < (unsigned)n) {
            int pos = g_off[d] + g_slot[i];
            if ((unsigned)pos < (unsigned)MAXE) g_csr[pos] = s;
        }
    }
}

// ---------------------------------------------------------------------------
// GEMM 128-col: g_h[n,128] = X[n,K] @ W[K,128]
// BM=128, BN=128, BK=16, 256 threads, per-thread 8x8, float4 everywhere,
// register-prefetch double buffering.
// ---------------------------------------------------------------------------
__global__ void gemm128(const float* __restrict__ Xext, int use_gx,
                        const float* __restrict__ W, int n, int K) {
    const float* __restrict__ X = use_gx ? (const float*)g_x : Xext;

    __shared__ float As[16][132];   // transposed, padded (132*4 % 16 == 0)
    __shared__ float Bs[16][128];

    const int tid = threadIdx.x;
    const int tx = tid & 15;
    const int ty = tid >> 4;
    const int row0 = blockIdx.x * 128;

    // A loader: row am, k-offset ak (8 contiguous k as 2 float4)
    const int am = tid >> 1;
    const int ak = (tid & 1) * 8;
    // B loader: rows bk,bk+8, col quad bq
    const int bk = tid >> 5;
    const int bq = (tid & 31) * 4;

    float acc[8][8] = {};
    float4 pa0, pa1, pb0, pb1;
    const int T = K >> 4;
    const float4 z4 = make_float4(0.f, 0.f, 0.f, 0.f);

    {   // prologue: tile 0
        int r = row0 + am;
        const float* xp = X + (size_t)r * K + ak;
        pa0 = (r < n) ? *(const float4*)(xp)     : z4;
        pa1 = (r < n) ? *(const float4*)(xp + 4) : z4;
        pb0 = *(const float4*)(W + (size_t)bk * 128 + bq);
        pb1 = *(const float4*)(W + (size_t)(bk + 8) * 128 + bq);
    }

    for (int t = 0; t < T; t++) {
        As[ak + 0][am] = pa0.x; As[ak + 1][am] = pa0.y;
        As[ak + 2][am] = pa0.z; As[ak + 3][am] = pa0.w;
        As[ak + 4][am] = pa1.x; As[ak + 5][am] = pa1.y;
        As[ak + 6][am] = pa1.z; As[ak + 7][am] = pa1.w;
        *(float4*)&Bs[bk][bq]     = pb0;
        *(float4*)&Bs[bk + 8][bq] = pb1;
        __syncthreads();

        if (t + 1 < T) {   // prefetch next tile (hidden under compute)
            int k0 = (t + 1) << 4;
            int r = row0 + am;
            const float* xp = X + (size_t)r * K + k0 + ak;
            pa0 = (r < n) ? *(const float4*)(xp)     : z4;
            pa1 = (r < n) ? *(const float4*)(xp + 4) : z4;
            pb0 = *(const float4*)(W + (size_t)(k0 + bk) * 128 + bq);
            pb1 = *(const float4*)(W + (size_t)(k0 + bk + 8) * 128 + bq);
        }

        #pragma unroll
        for (int kk = 0; kk < 16; kk++) {
            float a[8], b[8];
            *(float4*)(a)     = *(const float4*)&As[kk][ty * 4];
            *(float4*)(a + 4) = *(const float4*)&As[kk][64 + ty * 4];
            *(float4*)(b)     = *(const float4*)&Bs[kk][tx * 4];
            *(float4*)(b + 4) = *(const float4*)&Bs[kk][64 + tx * 4];
            #pragma unroll
            for (int r = 0; r < 8; r++)
                #pragma unroll
                for (int c = 0; c < 8; c++)
                    acc[r][c] = fmaf(a[r], b[c], acc[r][c]);
        }
        __syncthreads();
    }

    #pragma unroll
    for (int r = 0; r < 8; r++) {
        int rr = row0 + ((r < 4) ? ty * 4 + r : 64 + ty * 4 + r - 4);
        if (rr < n) {
            float4 v0 = make_float4(acc[r][0], acc[r][1], acc[r][2], acc[r][3]);
            float4 v1 = make_float4(acc[r][4], acc[r][5], acc[r][6], acc[r][7]);
            *(float4*)&g_h[(size_t)rr * 128 + tx * 4]      = v0;
            *(float4*)&g_h[(size_t)rr * 128 + 64 + tx * 4] = v1;
        }
    }
}

// ---------------------------------------------------------------------------
// GEMM 64-col: g_h[n,64] = X[n,128] @ W[128,64]  (X = g_x), per-thread 8x4
// ---------------------------------------------------------------------------
__global__ void gemm64(const float* __restrict__ W, int n) {
    const float* __restrict__ X = (const float*)g_x;
    const int K = 128;

    __shared__ float As[16][132];
    __shared__ float Bs[16][64];

    const int tid = threadIdx.x;
    const int tx = tid & 15;
    const int ty = tid >> 4;
    const int row0 = blockIdx.x * 128;

    const int am = tid >> 1;
    const int ak = (tid & 1) * 8;
    const int bk = tid >> 4;       // 16 rows, one quad each
    const int bq = (tid & 15) * 4;

    float acc[8][4] = {};
    float4 pa0, pa1, pb0;
    const int T = K >> 4;  // 8
    const float4 z4 = make_float4(0.f, 0.f, 0.f, 0.f);

    {
        int r = row0 + am;
        const float* xp = X + (size_t)r * K + ak;
        pa0 = (r < n) ? *(const float4*)(xp)     : z4;
        pa1 = (r < n) ? *(const float4*)(xp + 4) : z4;
        pb0 = *(const float4*)(W + (size_t)bk * 64 + bq);
    }

    for (int t = 0; t < T; t++) {
        As[ak + 0][am] = pa0.x; As[ak + 1][am] = pa0.y;
        As[ak + 2][am] = pa0.z; As[ak + 3][am] = pa0.w;
        As[ak + 4][am] = pa1.x; As[ak + 5][am] = pa1.y;
        As[ak + 6][am] = pa1.z; As[ak + 7][am] = pa1.w;
        *(float4*)&Bs[bk][bq] = pb0;
        __syncthreads();

        if (t + 1 < T) {
            int k0 = (t + 1) << 4;
            int r = row0 + am;
            const float* xp = X + (size_t)r * K + k0 + ak;
            pa0 = (r < n) ? *(const float4*)(xp)     : z4;
            pa1 = (r < n) ? *(const float4*)(xp + 4) : z4;
            pb0 = *(const float4*)(W + (size_t)(k0 + bk) * 64 + bq);
        }

        #pragma unroll
        for (int kk = 0; kk < 16; kk++) {
            float a[8], b[4];
            *(float4*)(a)     = *(const float4*)&As[kk][ty * 4];
            *(float4*)(a + 4) = *(const float4*)&As[kk][64 + ty * 4];
            *(float4*)(b)     = *(const float4*)&Bs[kk][tx * 4];
            #pragma unroll
            for (int r = 0; r < 8; r++)
                #pragma unroll
                for (int c = 0; c < 4; c++)
                    acc[r][c] = fmaf(a[r], b[c], acc[r][c]);
        }
        __syncthreads();
    }

    #pragma unroll
    for (int r = 0; r < 8; r++) {
        int rr = row0 + ((r < 4) ? ty * 4 + r : 64 + ty * 4 + r - 4);
        if (rr < n) {
            float4 v = make_float4(acc[r][0], acc[r][1], acc[r][2], acc[r][3]);
            *(float4*)&g_h[(size_t)rr * 64 + tx * 4] = v;
        }
    }
}

// ---------------------------------------------------------------------------
// Aggregation: g_x[i] = relu( dis[i]*(dis[i]*g_h[i] + sum_in dis[s]*g_h[s]) + b )
// One block per node, thread = feature. g_h (25.6MB) fits L2.
// ---------------------------------------------------------------------------
__global__ void agg128_relu(const float* __restrict__ bias, int n) {
    int node = blockIdx.x;
    int f = threadIdx.x;
    const float* __restrict__ h = (const float*)g_h;
    float dn = g_dis[node];
    float acc = dn * h[(size_t)node * 128 + f];
    int j = g_off[node], end = g_off[node + 1];
    for (; j < end; ++j) {
        int s = g_csr[j];
        acc = fmaf(g_dis[s], h[(size_t)s * 128 + f], acc);
    }
    float v = fmaf(dn, acc, bias[f]);
    g_x[(size_t)node * 128 + f] = fmaxf(v, 0.f);
}

// Layer-3 aggregation fused with log_softmax over 64 features.
__global__ void agg64_lsm(const float* __restrict__ bias,
                          float* __restrict__ out, int n) {
    int node = blockIdx.x;
    int f = threadIdx.x;   // 64
    const float* __restrict__ h = (const float*)g_h;
    float dn = g_dis[node];
    float acc = dn * h[(size_t)node * 64 + f];
    int j = g_off[node], end = g_off[node + 1];
    for (; j < end; ++j) {
        int s = g_csr[j];
        acc = fmaf(g_dis[s], h[(size_t)s * 64 + f], acc);
    }
    float v = fmaf(dn, acc, bias[f]);

    __shared__ float red[2];
    int w = f >> 5;
    float m = v;
    #pragma unroll
    for (int o = 16; o; o >>= 1) m = fmaxf(m, __shfl_xor_sync(0xffffffffu, m, o));
    if ((f & 31) == 0) red[w] = m;
    __syncthreads();
    m = fmaxf(red[0], red[1]);
    __syncthreads();
    float e = expf(v - m);
    float s2 = e;
    #pragma unroll
    for (int o = 16; o; o >>= 1) s2 += __shfl_xor_sync(0xffffffffu, s2, o);
    if ((f & 31) == 0) red[w] = s2;
    __syncthreads();
    float l = m + logf(red[0] + red[1]);
    out[(size_t)node * 64 + f] = v - l;
}

// ---------------------------------------------------------------------------
extern "C" void kernel_launch(void* const* d_in, const int* in_sizes, int n_in,
                              void* d_out, int out_size) {
    const float* feats = (const float*)d_in[0];
    const int*   adj   = (const int*)d_in[1];     // int32 (jax x64 disabled)
    const float* W1    = (const float*)d_in[2];
    const float* b1    = (const float*)d_in[3];
    const float* W2    = (const float*)d_in[4];
    const float* b2    = (const float*)d_in[5];
    const float* W3    = (const float*)d_in[6];
    const float* b3    = (const float*)d_in[7];
    float*       out   = (float*)d_out;

    const int N = in_sizes[0] / IN_DIM;
    const int E = in_sizes[1] / 2;
    const int* src = adj;
    const int* dst = adj + E;
    const int nb = (N + SCAN_BLK - 1) / SCAN_BLK;

    // --- preprocessing: CSR by dst, dis = deg^-1/2 ---
    init_deg<<<(N + 255) / 256, 256>>>(N);
    count_deg<<<(E + 255) / 256, 256>>>(dst, E, N);
    scan_partial<<<nb, SCAN_BLK>>>(N);
    scan_bsum<<<1, 64>>>(nb, N);
    add_off_dis<<<(N + 255) / 256, 256>>>(N);
    fill_csr<<<(E + 255) / 256, 256>>>(src, dst, E, N);

    const int gB = (N + 127) / 128;
    // --- layer 1: 512 -> 128, relu ---
    gemm128<<<gB, 256>>>(feats, 0, W1, N, IN_DIM);
    agg128_relu<<<N, 128>>>(b1, N);
    // --- layer 2: 128 -> 128, relu ---
    gemm128<<<gB, 256>>>(nullptr, 1, W2, N, HID);
    agg128_relu<<<N, 128>>>(b2, N);
    // --- layer 3: 128 -> 64, log_softmax (fused) ---
    gemm64<<<gB, 256>>>(W3, N);
    agg64_lsm<<<N, 64>>>(b3, out, N);
}

// round 6
// speedup vs baseline: 1.8770x; 1.1567x over previous
#include <cuda_runtime.h>
#include <cuda_bf16.h>
#include <mma.h>
#include <math.h>
#include <stdint.h>

using namespace nvcuda;

#define IN_DIM 512
#define HID    128
#define MAXN   50176
#define MAXE   800000
#define SCAN_BLK 1024

// -------------------- device-global scratch --------------------
__device__ float g_h[(size_t)MAXN * 128];   // GEMM output
__device__ float g_x[(size_t)MAXN * 128];   // aggregated activations
__device__ float g_dis[MAXN];
__device__ int   g_deg[MAXN];
__device__ int   g_off[MAXN + 1];
__device__ int   g_slot[MAXE];
__device__ int   g_csr[MAXE];
__device__ int   g_bsum[64];
__device__ int   g_boff[64];
// pre-split weights, bf16, [K,F] row-major (hi + lo)
__device__ __nv_bfloat16 g_w1h[512 * 128], g_w1l[512 * 128];
__device__ __nv_bfloat16 g_w2h[128 * 128], g_w2l[128 * 128];
__device__ __nv_bfloat16 g_w3h[128 * 64],  g_w3l[128 * 64];

// -------------------- graph preprocessing --------------------
__global__ void init_deg(int n) {
    int i = blockIdx.x * blockDim.x + threadIdx.x;
    if (i < n) g_deg[i] = 1;  // self loop
}
__global__ void count_deg(const int* __restrict__ dst, int e, int n) {
    int i = blockIdx.x * blockDim.x + threadIdx.x;
    if (i < e) {
        int d = dst[i];
        if ((unsigned)d < (unsigned)n) {
            int old = atomicAdd(&g_deg[d], 1);
            g_slot[i] = old - 1;
        }
    }
}
__global__ void scan_partial(int n) {
    __shared__ int s[SCAN_BLK];
    int b = blockIdx.x, tid = threadIdx.x;
    int i = b * SCAN_BLK + tid;
    int v = (i < n) ? (g_deg[i] - 1) : 0;
    s[tid] = v;
    __syncthreads();
    #pragma unroll
    for (int o = 1; o < SCAN_BLK; o <<= 1) {
        int t = (tid >= o) ? s[tid - o] : 0;
        __syncthreads();
        s[tid] += t;
        __syncthreads();
    }
    if (i < n) g_off[i] = s[tid] - v;
    if (tid == SCAN_BLK - 1) g_bsum[b] = s[tid];
}
__global__ void scan_bsum(int nb, int n) {
    __shared__ int s[64];
    int tid = threadIdx.x;
    int v = (tid < nb) ? g_bsum[tid] : 0;
    s[tid] = v;
    __syncthreads();
    #pragma unroll
    for (int o = 1; o < 64; o <<= 1) {
        int t = (tid >= o) ? s[tid - o] : 0;
        __syncthreads();
        s[tid] += t;
        __syncthreads();
    }
    if (tid < nb) g_boff[tid] = s[tid] - v;
    if (tid == 63) g_off[n] = s[63];
}
__global__ void add_off_dis(int n) {
    int i = blockIdx.x * blockDim.x + threadIdx.x;
    if (i < n) {
        g_off[i] += g_boff[i >> 10];
        g_dis[i] = rsqrtf((float)g_deg[i]);
    }
}
__global__ void fill_csr(const int* __restrict__ src,
                         const int* __restrict__ dst, int e, int n) {
    int i = blockIdx.x * blockDim.x + threadIdx.x;
    if (i < e) {
        int d = dst[i];
        int s = src[i];
        if ((unsigned)d < (unsigned)n && (unsigned)s < (unsigned)n) {
            int pos = g_off[d] + g_slot[i];
            if ((unsigned)pos < (unsigned)MAXE) g_csr[pos] = s;
        }
    }
}

// -------------------- weight split (fp32 -> bf16 hi + lo), [K,F] kept --------
__global__ void wsplit(const float* __restrict__ W, int KF, int sel) {
    int i = blockIdx.x * blockDim.x + threadIdx.x;
    if (i >= KF) return;
    float x = W[i];
    __nv_bfloat16 h = __float2bfloat16_rn(x);
    float l = x - __bfloat162float(h);
    __nv_bfloat16* Wh = (sel == 0) ? g_w1h : (sel == 1) ? g_w2h : g_w3h;
    __nv_bfloat16* Wl = (sel == 0) ? g_w1l : (sel == 1) ? g_w2l : g_w3l;
    Wh[i] = h;
    Wl[i] = __float2bfloat16_rn(l);
}

// -------------------- WMMA bf16 split GEMM ---------------------------------
// g_h[n,BN] = X[n,K] @ W[K,BN], D = Ahi*Bhi + Ahi*Blo + Alo*Bhi (fp32 accum).
// 256 threads (8 warps: 4 in M x 2 in N). Block tile 128 x BN, BK = 32.
// Warp tile 32 x (BN/2). Register prefetch of the A tile hides LDG.
template <int BN>
__global__ void __launch_bounds__(256)
wgemm(const float* __restrict__ Xext, int use_gx, int wsel, int n, int K) {
    constexpr int LDA = 40;        // 32 + 8 pad (bf16 elems)
    constexpr int LDB = BN + 8;
    constexpr int WN  = BN / 2;    // warp N span
    constexpr int JT  = WN / 16;   // j tiles per warp (4 or 2)

    __shared__ __nv_bfloat16 Ah[128 * LDA], Al[128 * LDA];
    __shared__ __nv_bfloat16 Bh[32 * LDB],  Bl[32 * LDB];

    const float* __restrict__ X = use_gx ? (const float*)g_x : Xext;
    const __nv_bfloat16* __restrict__ Wh =
        (wsel == 0) ? g_w1h : (wsel == 1) ? g_w2h : g_w3h;
    const __nv_bfloat16* __restrict__ Wl =
        (wsel == 0) ? g_w1l : (wsel == 1) ? g_w2l : g_w3l;

    const int tid = threadIdx.x;
    const int wid = tid >> 5;
    const int wm = wid & 3;        // 0..3 (M)
    const int wn = wid >> 2;       // 0..1 (N)
    const int row0 = blockIdx.x * 128;

    wmma::fragment<wmma::accumulator, 16, 16, 16, float> acc[2][JT];
    #pragma unroll
    for (int i = 0; i < 2; i++)
        #pragma unroll
        for (int j = 0; j < JT; j++) wmma::fill_fragment(acc[i][j], 0.0f);

    // A prefetch: 128x32 f32 = 1024 float4; 4 per thread
    float4 pa[4];
    const float4 z4 = make_float4(0.f, 0.f, 0.f, 0.f);
    {
        #pragma unroll
        for (int p = 0; p < 4; p++) {
            int f = tid + p * 256;
            int r = f >> 3, c = f & 7;
            int gr = row0 + r;
            pa[p] = (gr < n) ? *(const float4*)(X + (size_t)gr * K + c * 4) : z4;
        }
    }

    const int T = K >> 5;
    for (int t = 0; t < T; t++) {
        // --- stage A (split hi/lo) ---
        #pragma unroll
        for (int p = 0; p < 4; p++) {
            int f = tid + p * 256;
            int r = f >> 3, c = f & 7;
            float4 v = pa[p];
            __nv_bfloat16 h0 = __float2bfloat16_rn(v.x);
            __nv_bfloat16 h1 = __float2bfloat16_rn(v.y);
            __nv_bfloat16 h2 = __float2bfloat16_rn(v.z);
            __nv_bfloat16 h3 = __float2bfloat16_rn(v.w);
            __nv_bfloat162 hp0 = __nv_bfloat162(h0, h1);
            __nv_bfloat162 hp1 = __nv_bfloat162(h2, h3);
            __nv_bfloat162 lp0 = __nv_bfloat162(
                __float2bfloat16_rn(v.x - __bfloat162float(h0)),
                __float2bfloat16_rn(v.y - __bfloat162float(h1)));
            __nv_bfloat162 lp1 = __nv_bfloat162(
                __float2bfloat16_rn(v.z - __bfloat162float(h2)),
                __float2bfloat16_rn(v.w - __bfloat162float(h3)));
            uint2 hw, lw;
            hw.x = *(uint32_t*)&hp0; hw.y = *(uint32_t*)&hp1;
            lw.x = *(uint32_t*)&lp0; lw.y = *(uint32_t*)&lp1;
            *(uint2*)&Ah[r * LDA + c * 4] = hw;
            *(uint2*)&Al[r * LDA + c * 4] = lw;
        }
        // --- stage B (pre-split bf16, [K,BN]) ---
        const int k0 = t << 5;
        if (BN == 128) {
            #pragma unroll
            for (int p = 0; p < 2; p++) {
                int idx = tid + p * 256;
                int r = idx >> 4, c8 = idx & 15;
                *(uint4*)&Bh[r * LDB + c8 * 8] =
                    *(const uint4*)(Wh + (size_t)(k0 + r) * BN + c8 * 8);
                *(uint4*)&Bl[r * LDB + c8 * 8] =
                    *(const uint4*)(Wl + (size_t)(k0 + r) * BN + c8 * 8);
            }
        } else {
            int r = tid >> 3, c8 = tid & 7;
            *(uint4*)&Bh[r * LDB + c8 * 8] =
                *(const uint4*)(Wh + (size_t)(k0 + r) * BN + c8 * 8);
            *(uint4*)&Bl[r * LDB + c8 * 8] =
                *(const uint4*)(Wl + (size_t)(k0 + r) * BN + c8 * 8);
        }
        __syncthreads();

        if (t + 1 < T) {   // prefetch next A tile
            int kn = (t + 1) << 5;
            #pragma unroll
            for (int p = 0; p < 4; p++) {
                int f = tid + p * 256;
                int r = f >> 3, c = f & 7;
                int gr = row0 + r;
                pa[p] = (gr < n) ? *(const float4*)(X + (size_t)gr * K + kn + c * 4)
                                 : z4;
            }
        }

        #pragma unroll
        for (int ks = 0; ks < 2; ks++) {
            wmma::fragment<wmma::matrix_a, 16, 16, 16, __nv_bfloat16,
                           wmma::row_major> ah[2], al[2];
            #pragma unroll
            for (int i = 0; i < 2; i++) {
                const __nv_bfloat16* ap = &Ah[(wm * 32 + i * 16) * LDA + ks * 16];
                const __nv_bfloat16* lp = &Al[(wm * 32 + i * 16) * LDA + ks * 16];
                wmma::load_matrix_sync(ah[i], ap, LDA);
                wmma::load_matrix_sync(al[i], lp, LDA);
            }
            #pragma unroll
            for (int j = 0; j < JT; j++) {
                wmma::fragment<wmma::matrix_b, 16, 16, 16, __nv_bfloat16,
                               wmma::row_major> bh, bl;
                wmma::load_matrix_sync(bh, &Bh[ks * 16 * LDB + wn * WN + j * 16], LDB);
                wmma::load_matrix_sync(bl, &Bl[ks * 16 * LDB + wn * WN + j * 16], LDB);
                #pragma unroll
                for (int i = 0; i < 2; i++) {
                    wmma::mma_sync(acc[i][j], ah[i], bh, acc[i][j]);
                    wmma::mma_sync(acc[i][j], ah[i], bl, acc[i][j]);
                    wmma::mma_sync(acc[i][j], al[i], bh, acc[i][j]);
                }
            }
        }
        __syncthreads();
    }

    // --- epilogue: direct fp32 store (rows beyond n are scratch, in-bounds) ---
    #pragma unroll
    for (int i = 0; i < 2; i++) {
        int r = row0 + wm * 32 + i * 16;
        #pragma unroll
        for (int j = 0; j < JT; j++) {
            int c = wn * WN + j * 16;
            wmma::store_matrix_sync(&g_h[(size_t)r * BN + c], acc[i][j], BN,
                                    wmma::mem_row_major);
        }
    }
}

// -------------------- aggregation --------------------
__global__ void agg128_relu(const float* __restrict__ bias, int n) {
    int node = blockIdx.x;
    int f = threadIdx.x;
    const float* __restrict__ h = (const float*)g_h;
    float dn = g_dis[node];
    float acc = dn * h[(size_t)node * 128 + f];
    int j = g_off[node], end = g_off[node + 1];
    for (; j < end; ++j) {
        int s = g_csr[j];
        acc = fmaf(g_dis[s], h[(size_t)s * 128 + f], acc);
    }
    float v = fmaf(dn, acc, bias[f]);
    g_x[(size_t)node * 128 + f] = fmaxf(v, 0.f);
}

__global__ void agg64_lsm(const float* __restrict__ bias,
                          float* __restrict__ out, int n) {
    int node = blockIdx.x;
    int f = threadIdx.x;   // 64
    const float* __restrict__ h = (const float*)g_h;
    float dn = g_dis[node];
    float acc = dn * h[(size_t)node * 64 + f];
    int j = g_off[node], end = g_off[node + 1];
    for (; j < end; ++j) {
        int s = g_csr[j];
        acc = fmaf(g_dis[s], h[(size_t)s * 64 + f], acc);
    }
    float v = fmaf(dn, acc, bias[f]);

    __shared__ float red[2];
    int w = f >> 5;
    float m = v;
    #pragma unroll
    for (int o = 16; o; o >>= 1) m = fmaxf(m, __shfl_xor_sync(0xffffffffu, m, o));
    if ((f & 31) == 0) red[w] = m;
    __syncthreads();
    m = fmaxf(red[0], red[1]);
    __syncthreads();
    float e = expf(v - m);
    float s2 = e;
    #pragma unroll
    for (int o = 16; o; o >>= 1) s2 += __shfl_xor_sync(0xffffffffu, s2, o);
    if ((f & 31) == 0) red[w] = s2;
    __syncthreads();
    float l = m + logf(red[0] + red[1]);
    out[(size_t)node * 64 + f] = v - l;
}

// -------------------- launch --------------------
extern "C" void kernel_launch(void* const* d_in, const int* in_sizes, int n_in,
                              void* d_out, int out_size) {
    const float* feats = (const float*)d_in[0];
    const int*   adj   = (const int*)d_in[1];     // int32 (jax x64 disabled)
    const float* W1    = (const float*)d_in[2];
    const float* b1    = (const float*)d_in[3];
    const float* W2    = (const float*)d_in[4];
    const float* b2    = (const float*)d_in[5];
    const float* W3    = (const float*)d_in[6];
    const float* b3    = (const float*)d_in[7];
    float*       out   = (float*)d_out;

    const int N = in_sizes[0] / IN_DIM;
    const int E = in_sizes[1] / 2;
    const int* src = adj;
    const int* dst = adj + E;
    const int nb = (N + SCAN_BLK - 1) / SCAN_BLK;

    // --- preprocessing ---
    init_deg<<<(N + 255) / 256, 256>>>(N);
    count_deg<<<(E + 255) / 256, 256>>>(dst, E, N);
    scan_partial<<<nb, SCAN_BLK>>>(N);
    scan_bsum<<<1, 64>>>(nb, N);
    add_off_dis<<<(N + 255) / 256, 256>>>(N);
    fill_csr<<<(E + 255) / 256, 256>>>(src, dst, E, N);
    wsplit<<<(IN_DIM * HID + 255) / 256, 256>>>(W1, IN_DIM * HID, 0);
    wsplit<<<(HID * HID + 255) / 256, 256>>>(W2, HID * HID, 1);
    wsplit<<<(HID * 64 + 255) / 256, 256>>>(W3, HID * 64, 2);

    const int gB = (N + 127) / 128;
    // --- layer 1: 512 -> 128, relu ---
    wgemm<128><<<gB, 256>>>(feats, 0, 0, N, IN_DIM);
    agg128_relu<<<N, 128>>>(b1, N);
    // --- layer 2: 128 -> 128, relu ---
    wgemm<128><<<gB, 256>>>(nullptr, 1, 1, N, HID);
    agg128_relu<<<N, 128>>>(b2, N);
    // --- layer 3: 128 -> 64, log_softmax (fused) ---
    wgemm<64><<<gB, 256>>>(nullptr, 1, 2, N, HID);
    agg64_lsm<<<N, 64>>>(b3, out, N);
}